// round 16
// baseline (speedup 1.0000x reference)
#include <cuda_runtime.h>
#include <cuda_fp16.h>
#include <stdint.h>
#include <math.h>

#define HID 128
#define NU_MAX 100000
#define NI_MAX 50000

// Node projections stored fp16 (b0 folded into the "src" side).
__device__ __half g_user_pre[2][(size_t)NU_MAX * HID];
__device__ __half g_item_pre[2][(size_t)NI_MAX * HID];

__device__ __forceinline__ uint32_t smem_u32(const void* p) {
    uint32_t a;
    asm("{ .reg .u64 t; cvta.to.shared.u64 t, %1; cvt.u32.u64 %0, t; }"
        : "=r"(a) : "l"(p));
    return a;
}

__device__ __forceinline__ float elu_f(float x) {
    return x > 0.f ? x : (__expf(x) - 1.f);
}

// half2 ELU: x>0 ? x : exp(x)-1, NaN-safe (exp arg clamped to <=0)
__device__ __forceinline__ __half2 elu_h2(__half2 x) {
    const __half2 zero = __float2half2_rn(0.f);
    const __half2 one  = __float2half2_rn(1.f);
    __half2 m  = __hgt2(x, zero);
    __half2 e  = __hsub2(h2exp(__hmin2(x, zero)), one);
    return __hfma2(m, __hsub2(x, e), e);
}

__device__ __forceinline__ void mma_sync_f16(float4& d, const uint32_t a[4], uint2 b) {
    asm volatile(
        "mma.sync.aligned.m16n8k16.row.col.f32.f16.f16.f32 "
        "{%0,%1,%2,%3}, {%4,%5,%6,%7}, {%8,%9}, {%0,%1,%2,%3};"
        : "+f"(d.x), "+f"(d.y), "+f"(d.z), "+f"(d.w)
        : "r"(a[0]), "r"(a[1]), "r"(a[2]), "r"(a[3]), "r"(b.x), "r"(b.y));
}

__device__ __forceinline__ uint4 ldcg_u4(const void* g) {
    uint4 r;
    asm volatile("ld.global.cg.v4.u32 {%0,%1,%2,%3}, [%4];"
                 : "=r"(r.x), "=r"(r.y), "=r"(r.z), "=r"(r.w) : "l"(g));
    return r;
}

// Paired pack: lane entry = uint4 holding fragments for nt=2*np and nt=2*np+1.
__device__ __forceinline__ void pack_B_frag2(__half* Bsh, const float* __restrict__ W, int tid) {
    for (int e2 = tid; e2 < 2048; e2 += 256) {
        int ks = e2 >> 8;
        int np = (e2 >> 5) & 7;
        int lane = e2 & 31;
        int g = lane >> 2, t = lane & 3;
        int k0 = ks * 16 + 2 * t;
        __half2* dst = (__half2*)(Bsh + (size_t)e2 * 8);
        #pragma unroll
        for (int sub = 0; sub < 2; sub++) {
            int n = (2 * np + sub) * 8 + g;
            dst[sub * 2 + 0] = __floats2half2_rn(W[k0 * 128 + n],       W[(k0 + 1) * 128 + n]);
            dst[sub * 2 + 1] = __floats2half2_rn(W[(k0 + 8) * 128 + n], W[(k0 + 9) * 128 + n]);
        }
    }
}

// ===========================================================================
// Precompute: outA = emb@Wa + biasA, outB = emb@Wb (fp16 outputs).
// ===========================================================================
#define LDH 136
#define BSH_H 16384
#define ASH_PRE_H (128 * LDH)
#define SMEM_PRE_BYTES (BSH_H*2*2 + ASH_PRE_H*2)

__device__ __forceinline__ void mma_tile_pair(const __half* Ash, const __half* Bsh,
                                              int warp_m, int warp_n, int lane,
                                              float4 D[2][8]) {
    const int g = lane >> 2, t = lane & 3;
    #pragma unroll
    for (int m = 0; m < 2; m++)
        #pragma unroll
        for (int j = 0; j < 8; j++) D[m][j] = make_float4(0.f, 0.f, 0.f, 0.f);

    #pragma unroll
    for (int ks = 0; ks < 8; ks++) {
        uint32_t a[2][4];
        #pragma unroll
        for (int m = 0; m < 2; m++) {
            const __half* Ar = Ash + (warp_m * 32 + m * 16 + g) * LDH + ks * 16 + 2 * t;
            a[m][0] = *(const uint32_t*)Ar;
            a[m][1] = *(const uint32_t*)(Ar + 8 * LDH);
            a[m][2] = *(const uint32_t*)(Ar + 8);
            a[m][3] = *(const uint32_t*)(Ar + 8 * LDH + 8);
        }
        const uint4* Bp = (const uint4*)Bsh + (ks * 8 + warp_n * 4) * 32 + lane;
        #pragma unroll
        for (int jp = 0; jp < 4; jp++) {
            uint4 bb = Bp[jp * 32];
            uint2 blo = make_uint2(bb.x, bb.y);
            uint2 bhi = make_uint2(bb.z, bb.w);
            mma_sync_f16(D[0][jp * 2 + 0], a[0], blo);
            mma_sync_f16(D[1][jp * 2 + 0], a[1], blo);
            mma_sync_f16(D[0][jp * 2 + 1], a[0], bhi);
            mma_sync_f16(D[1][jp * 2 + 1], a[1], bhi);
        }
    }
}

__global__ void __launch_bounds__(256, 2)
pre_merged(const float* __restrict__ embU,
           const float* __restrict__ WaU, const float* __restrict__ WbU,
           const float* __restrict__ biasAU,
           __half* __restrict__ outAU, __half* __restrict__ outBU, int nU,
           const float* __restrict__ embI,
           const float* __restrict__ WaI, const float* __restrict__ WbI,
           const float* __restrict__ biasAI,
           __half* __restrict__ outAI, __half* __restrict__ outBI, int nI)
{
    extern __shared__ char smraw[];
    __half* BshA = (__half*)smraw;
    __half* BshB = BshA + BSH_H;
    __half* Ash  = BshB + BSH_H;

    const int tid  = threadIdx.x;
    const int lane = tid & 31, wid = tid >> 5;
    const int warp_m = wid & 3, warp_n = wid >> 2;
    const int g = lane >> 2, t = lane & 3;
    const int cbase = warp_n * 64 + 2 * t;

    const int half_grid = gridDim.x >> 1;
    const bool second = blockIdx.x >= half_grid;
    const float* emb = second ? embI : embU;
    const float* Wa  = second ? WaI  : WaU;
    const float* Wb  = second ? WbI  : WbU;
    const float* biasA = second ? biasAI : biasAU;
    __half* outA = second ? outAI : outAU;
    __half* outB = second ? outBI : outBU;
    const int rows = second ? nI : nU;
    const int bstart = blockIdx.x - (second ? half_grid : 0);

    pack_B_frag2(BshA, Wa, tid);
    pack_B_frag2(BshB, Wb, tid);

    float2 bA[8];
    #pragma unroll
    for (int j = 0; j < 8; j++)
        bA[j] = ((const float2*)biasA)[(cbase + j * 8) >> 1];
    __syncthreads();

    const int ntiles = (rows + 127) >> 7;
    for (int tile = bstart; tile < ntiles; tile += half_grid) {
        const int m0 = tile << 7;
        #pragma unroll
        for (int i = tid; i < 128 * 32; i += 256) {
            int r = i >> 5, c = i & 31;
            int row = m0 + r;
            float4 v = make_float4(0.f, 0.f, 0.f, 0.f);
            if (row < rows) v = __ldcs((const float4*)(emb + (size_t)row * HID) + c);
            __half2 hh[2];
            hh[0] = __floats2half2_rn(v.x, v.y);
            hh[1] = __floats2half2_rn(v.z, v.w);
            *(uint2*)(Ash + r * LDH + c * 4) = *(uint2*)hh;
        }
        __syncthreads();

        #pragma unroll
        for (int pass = 0; pass < 2; pass++) {
            const __half* Bsh = pass ? BshB : BshA;
            __half* outP = pass ? outB : outA;
            float4 D[2][8];
            mma_tile_pair(Ash, Bsh, warp_m, warp_n, lane, D);
            #pragma unroll
            for (int m = 0; m < 2; m++) {
                int r0 = m0 + warp_m * 32 + m * 16 + g;
                #pragma unroll
                for (int j = 0; j < 8; j++) {
                    int c = cbase + j * 8;
                    float2 bb = pass ? make_float2(0.f, 0.f) : bA[j];
                    if (r0 < rows)
                        *(__half2*)(outP + (size_t)r0 * HID + c) =
                            __floats2half2_rn(D[m][j].x + bb.x, D[m][j].y + bb.y);
                    if (r0 + 8 < rows)
                        *(__half2*)(outP + (size_t)(r0 + 8) * HID + c) =
                            __floats2half2_rn(D[m][j].z + bb.x, D[m][j].w + bb.y);
                }
            }
        }
        __syncthreads();
    }
}

// ===========================================================================
// Edge kernel: single barrier per tile. Order per iteration:
//   build(tile+step) -> A[buf^1]   (no barrier before mma!)
//   mma(tile)        <- A[buf]
//   epilogue(tile)   -> red[buf]
//   __syncthreads()
//   output(tile)     <- red[buf]
// A double-buffered (writes of iter k vs reads of iter k+1 ordered by the
// sync at end of iter k). red double-buffered (epilogue(n+1) may overlap
// output(n)). fp32 epilogue (R13 numerics). 3 CTAs/SM.
// ===========================================================================
#define TILE    64
#define AROW    272                       // 136 halves
#define ABUF    (TILE * AROW)             // 17408
#define EB_B    0
#define EB_A0   32768
#define EB_A1   (EB_A0 + ABUF)            // 50176
#define EB_RED  (EB_A1 + ABUF)            // 67584 (2 x 256 floats)
#define EB_B1S  (EB_RED + 2048)           // 69632
#define EB_W2S  (EB_B1S + 512)            // 70144
#define SMEM_EDGE_BYTES (EB_W2S + 512)    // 70656

struct DecParams {
    const void* src;
    const void* dst;
    const __half* Psrc;
    const __half* Pdst;
    const float *b0, *W1, *b1, *W2, *b2;
    float* out;
};

__global__ void __launch_bounds__(256, 3)
edge_sb(DecParams p0, DecParams p1, int nE)
{
    extern __shared__ char smraw[];
    const uint32_t sbase = smem_u32(smraw);
    float*  redb = (float*)(smraw + EB_RED);
    float*  b1sh = (float*)(smraw + EB_B1S);
    float*  w2sh = (float*)(smraw + EB_W2S);

    const int tid  = threadIdx.x;
    const int lane = tid & 31, wid = tid >> 5;
    const int warp_m = wid & 1;           // 2 x 32 rows
    const int warp_n = wid >> 1;          // 4 x 32 cols
    const int g = lane >> 2, t = lane & 3;

    const int half_grid = gridDim.x >> 1;
    const bool second = blockIdx.x >= half_grid;
    const DecParams p = second ? p1 : p0;
    const int bstart = blockIdx.x - (second ? half_grid : 0);

    // int64 vs int32 indices (values < 2^17 -> int64 high words are 0)
    const int* sw = (const int*)p.src;
    int zz = 0;
    #pragma unroll
    for (int i = 1; i < 64; i += 2) zz |= sw[i];
    const bool is64 = (zz == 0);
    const int* srcw = (const int*)p.src;
    const int* dstw = (const int*)p.dst;
    const int imul = is64 ? 2 : 1;        // index word stride

    pack_B_frag2((__half*)(smraw + EB_B), p.W1, tid);
    if (tid < 128) {
        b1sh[tid] = p.b1[tid];
        w2sh[tid] = p.W2[tid];
    }
    const float bias2 = p.b2[0];

    // gather role: 4 threads per edge; thread covers 32 halves (64B) of the row
    const int grow = tid >> 2;            // edge row 0..63
    const int gq   = tid & 3;             // quarter 0..3
    const uint32_t a_stb = sbase + EB_A0 + (uint32_t)grow * AROW + (uint32_t)gq * 64;

    const int ntiles = (nE + TILE - 1) / TILE;
    const int step = half_grid;

    // helper expressed inline: build one tile into the given A buffer
    auto build = [&](uint32_t si, uint32_t di, uint32_t abuf_off) {
        const char* U = (const char*)p.Psrc + ((size_t)(si << 8)) + gq * 64;
        const char* V = (const char*)p.Pdst + ((size_t)(di << 8)) + gq * 64;
        #pragma unroll
        for (int j = 0; j < 4; j++) {
            uint4 u4 = ldcg_u4(U + j * 16);
            uint4 v4 = ldcg_u4(V + j * 16);
            const __half2* uh = (const __half2*)&u4;
            const __half2* vh = (const __half2*)&v4;
            __half2 hh[4];
            #pragma unroll
            for (int q = 0; q < 4; q++)
                hh[q] = elu_h2(__hadd2(uh[q], vh[q]));
            asm volatile("st.shared.v4.u32 [%0], {%1,%2,%3,%4};"
                         :: "r"(a_stb + abuf_off + j * 16),
                            "r"(((uint32_t*)hh)[0]), "r"(((uint32_t*)hh)[1]),
                            "r"(((uint32_t*)hh)[2]), "r"(((uint32_t*)hh)[3])
                         : "memory");
        }
    };

    // ---- prologue: build the first tile into A[0]; prefetch idx(t0+step)
    uint32_t si = 0, di = 0;
    if (bstart < ntiles) {
        int e = bstart * TILE + grow;
        uint32_t s0 = 0, d0 = 0;
        if (e < nE) {
            s0 = (uint32_t)__ldcs(srcw + (size_t)e * imul);
            d0 = (uint32_t)__ldcs(dstw + (size_t)e * imul);
        }
        build(s0, d0, 0);
        int e1 = (bstart + step) * TILE + grow;
        if (bstart + step < ntiles && e1 < nE) {
            si = (uint32_t)__ldcs(srcw + (size_t)e1 * imul);
            di = (uint32_t)__ldcs(dstw + (size_t)e1 * imul);
        }
    }
    __syncthreads();

    int it = 0;
    for (int tile = bstart; tile < ntiles; tile += step, it++) {
        const uint32_t buf = (uint32_t)(it & 1);
        float* red = redb + buf * 256;

        // --- build NEXT tile into A[buf^1] (no barrier before mma)
        if (tile + step < ntiles) {
            // prefetch indices for tile+2*step
            uint32_t nsi = 0, ndi = 0;
            {
                int nt2 = tile + 2 * step;
                if (nt2 < ntiles) {
                    int e2 = nt2 * TILE + grow;
                    if (e2 < nE) {
                        nsi = (uint32_t)__ldcs(srcw + (size_t)e2 * imul);
                        ndi = (uint32_t)__ldcs(dstw + (size_t)e2 * imul);
                    }
                }
            }
            build(si, di, (buf ^ 1u) * ABUF);
            si = nsi; di = ndi;
        }

        // --- layer-1 GEMM on A[buf]: ldmatrix A, paired-B LDS.128
        float4 D[2][4];
        #pragma unroll
        for (int m = 0; m < 2; m++)
            #pragma unroll
            for (int j = 0; j < 4; j++) D[m][j] = make_float4(0.f, 0.f, 0.f, 0.f);

        const int lrow = lane & 15;
        const int khalf = (lane >> 4) << 3;
        #pragma unroll
        for (int ks = 0; ks < 8; ks++) {
            uint32_t a[2][4];
            #pragma unroll
            for (int m = 0; m < 2; m++) {
                uint32_t addr = sbase + EB_A0 + buf * ABUF
                              + (uint32_t)(warp_m * 32 + m * 16 + lrow) * AROW
                              + (uint32_t)(ks * 16 + khalf) * 2;
                asm volatile("ldmatrix.sync.aligned.m8n8.x4.shared.b16 {%0,%1,%2,%3}, [%4];"
                             : "=r"(a[m][0]), "=r"(a[m][1]), "=r"(a[m][2]), "=r"(a[m][3])
                             : "r"(addr));
            }
            const uint4* Bp = (const uint4*)(smraw + EB_B)
                            + (ks * 8 + warp_n * 2) * 32 + lane;
            #pragma unroll
            for (int jp = 0; jp < 2; jp++) {
                uint4 bb = Bp[jp * 32];
                uint2 blo = make_uint2(bb.x, bb.y);
                uint2 bhi = make_uint2(bb.z, bb.w);
                mma_sync_f16(D[0][jp * 2 + 0], a[0], blo);
                mma_sync_f16(D[1][jp * 2 + 0], a[1], blo);
                mma_sync_f16(D[0][jp * 2 + 1], a[0], bhi);
                mma_sync_f16(D[1][jp * 2 + 1], a[1], bhi);
            }
        }

        // --- epilogue: fp32 elu(C + b1) . w2, quad-reduce -> red[buf]
        #pragma unroll
        for (int m = 0; m < 2; m++) {
            float plo = 0.f, phi = 0.f;
            #pragma unroll
            for (int j = 0; j < 4; j++) {
                int c = warp_n * 32 + j * 8 + 2 * t;
                float2 b1v = *(const float2*)(b1sh + c);
                float2 w2v = *(const float2*)(w2sh + c);
                plo += elu_f(D[m][j].x + b1v.x) * w2v.x
                     + elu_f(D[m][j].y + b1v.y) * w2v.y;
                phi += elu_f(D[m][j].z + b1v.x) * w2v.x
                     + elu_f(D[m][j].w + b1v.y) * w2v.y;
            }
            plo += __shfl_xor_sync(0xffffffffu, plo, 1);
            plo += __shfl_xor_sync(0xffffffffu, plo, 2);
            phi += __shfl_xor_sync(0xffffffffu, phi, 1);
            phi += __shfl_xor_sync(0xffffffffu, phi, 2);
            if (t == 0) {
                int r = warp_m * 32 + m * 16 + g;
                red[warp_n * 64 + r]     = plo;
                red[warp_n * 64 + r + 8] = phi;
            }
        }
        __syncthreads();                  // the ONLY barrier per tile

        // --- output (reads red[buf]; next iter's epilogue writes red[buf^1])
        if (tid < TILE) {
            int eo = tile * TILE + tid;
            if (eo < nE) {
                float x = red[tid] + red[64 + tid] + red[128 + tid] + red[192 + tid]
                        + bias2;
                __stcs(p.out + eo, 1.f / (1.f + __expf(-x)));
            }
        }
        // A[buf] (read by this iter's mma, done before the sync) is rebuilt
        // by NEXT iter's build, which runs after this sync. red[buf] is read
        // here; it is rewritten two iterations later (one sync in between).
    }
}

// ===========================================================================
extern "C" void kernel_launch(void* const* d_in, const int* in_sizes, int n_in,
                              void* d_out, int out_size)
{
    const float* user_emb = (const float*)d_in[0];
    const float* item_emb = (const float*)d_in[1];
    const void*  ui_src   = d_in[2];
    const void*  ui_dst   = d_in[3];
    const void*  iu_src   = d_in[4];
    const void*  iu_dst   = d_in[5];
    const float* W0_ui = (const float*)d_in[6];
    const float* b0_ui = (const float*)d_in[7];
    const float* W1_ui = (const float*)d_in[8];
    const float* b1_ui = (const float*)d_in[9];
    const float* W2_ui = (const float*)d_in[10];
    const float* b2_ui = (const float*)d_in[11];
    const float* W0_iu = (const float*)d_in[12];
    const float* b0_iu = (const float*)d_in[13];
    const float* W1_iu = (const float*)d_in[14];
    const float* b1_iu = (const float*)d_in[15];
    const float* W2_iu = (const float*)d_in[16];
    const float* b2_iu = (const float*)d_in[17];
    float* out = (float*)d_out;

    const int nU = in_sizes[0] / HID;
    const int nI = in_sizes[1] / HID;
    const int nE = in_sizes[2];

    cudaFuncSetAttribute(pre_merged,
                         cudaFuncAttributeMaxDynamicSharedMemorySize, SMEM_PRE_BYTES);
    cudaFuncSetAttribute(edge_sb,
                         cudaFuncAttributeMaxDynamicSharedMemorySize, SMEM_EDGE_BYTES);

    __half *up, *ip;
    cudaGetSymbolAddress((void**)&up, g_user_pre);
    cudaGetSymbolAddress((void**)&ip, g_item_pre);
    __half* U_ui = up;                          // user @ W0_ui[0:128] + b0_ui
    __half* U_iu = up + (size_t)NU_MAX * HID;   // user @ W0_iu[128:256]
    __half* I_ui = ip;                          // item @ W0_ui[128:256]
    __half* I_iu = ip + (size_t)NI_MAX * HID;   // item @ W0_iu[0:128] + b0_iu

    pre_merged<<<296, 256, SMEM_PRE_BYTES>>>(
        user_emb, W0_ui,           W0_iu + 128*128, b0_ui, U_ui, U_iu, nU,
        item_emb, W0_iu,           W0_ui + 128*128, b0_iu, I_iu, I_ui, nI);

    DecParams p0, p1;
    p0.src = ui_src; p0.dst = ui_dst; p0.Psrc = U_ui; p0.Pdst = I_ui;
    p0.b0 = b0_ui; p0.W1 = W1_ui; p0.b1 = b1_ui; p0.W2 = W2_ui; p0.b2 = b2_ui;
    p0.out = out;
    p1.src = iu_src; p1.dst = iu_dst; p1.Psrc = I_iu; p1.Pdst = U_iu;
    p1.b0 = b0_iu; p1.W1 = W1_iu; p1.b1 = b1_iu; p1.W2 = W2_iu; p1.b2 = b2_iu;
    p1.out = out + nE;

    edge_sb<<<444, 256, SMEM_EDGE_BYTES>>>(p0, p1, nE);
}

// round 17
// speedup vs baseline: 1.2273x; 1.2273x over previous
#include <cuda_runtime.h>
#include <cuda_fp16.h>
#include <stdint.h>
#include <math.h>

#define HID 128
#define NU_MAX 100000
#define NI_MAX 50000

// Node projections stored fp16 (b0 folded into the "src" side).
__device__ __half g_user_pre[2][(size_t)NU_MAX * HID];
__device__ __half g_item_pre[2][(size_t)NI_MAX * HID];

__device__ __forceinline__ uint32_t smem_u32(const void* p) {
    uint32_t a;
    asm("{ .reg .u64 t; cvta.to.shared.u64 t, %1; cvt.u32.u64 %0, t; }"
        : "=r"(a) : "l"(p));
    return a;
}

__device__ __forceinline__ float elu_f(float x) {
    return x > 0.f ? x : (__expf(x) - 1.f);
}

// half2 ELU: x>0 ? x : exp(x)-1, NaN-safe (exp arg clamped to <=0)
__device__ __forceinline__ __half2 elu_h2(__half2 x) {
    const __half2 zero = __float2half2_rn(0.f);
    const __half2 one  = __float2half2_rn(1.f);
    __half2 m  = __hgt2(x, zero);
    __half2 e  = __hsub2(h2exp(__hmin2(x, zero)), one);
    return __hfma2(m, __hsub2(x, e), e);
}

__device__ __forceinline__ void mma_sync_f16(float4& d, const uint32_t a[4], uint2 b) {
    asm volatile(
        "mma.sync.aligned.m16n8k16.row.col.f32.f16.f16.f32 "
        "{%0,%1,%2,%3}, {%4,%5,%6,%7}, {%8,%9}, {%0,%1,%2,%3};"
        : "+f"(d.x), "+f"(d.y), "+f"(d.z), "+f"(d.w)
        : "r"(a[0]), "r"(a[1]), "r"(a[2]), "r"(a[3]), "r"(b.x), "r"(b.y));
}

__device__ __forceinline__ uint4 ldcg_u4(const void* g) {
    uint4 r;
    asm volatile("ld.global.cg.v4.u32 {%0,%1,%2,%3}, [%4];"
                 : "=r"(r.x), "=r"(r.y), "=r"(r.z), "=r"(r.w) : "l"(g));
    return r;
}

// Paired pack: lane entry = uint4 holding fragments for nt=2*np and nt=2*np+1.
__device__ __forceinline__ void pack_B_frag2(__half* Bsh, const float* __restrict__ W, int tid) {
    for (int e2 = tid; e2 < 2048; e2 += 256) {
        int ks = e2 >> 8;
        int np = (e2 >> 5) & 7;
        int lane = e2 & 31;
        int g = lane >> 2, t = lane & 3;
        int k0 = ks * 16 + 2 * t;
        __half2* dst = (__half2*)(Bsh + (size_t)e2 * 8);
        #pragma unroll
        for (int sub = 0; sub < 2; sub++) {
            int n = (2 * np + sub) * 8 + g;
            dst[sub * 2 + 0] = __floats2half2_rn(W[k0 * 128 + n],       W[(k0 + 1) * 128 + n]);
            dst[sub * 2 + 1] = __floats2half2_rn(W[(k0 + 8) * 128 + n], W[(k0 + 9) * 128 + n]);
        }
    }
}

// ===========================================================================
// Precompute: outA = emb@Wa + biasA, outB = emb@Wb (fp16 outputs).
// Grid split user:item proportional to tile counts (passed as ublocks).
// ===========================================================================
#define LDH 136
#define BSH_H 16384
#define ASH_PRE_H (128 * LDH)
#define SMEM_PRE_BYTES (BSH_H*2*2 + ASH_PRE_H*2)

__device__ __forceinline__ void mma_tile_pair(const __half* Ash, const __half* Bsh,
                                              int warp_m, int warp_n, int lane,
                                              float4 D[2][8]) {
    const int g = lane >> 2, t = lane & 3;
    #pragma unroll
    for (int m = 0; m < 2; m++)
        #pragma unroll
        for (int j = 0; j < 8; j++) D[m][j] = make_float4(0.f, 0.f, 0.f, 0.f);

    #pragma unroll
    for (int ks = 0; ks < 8; ks++) {
        uint32_t a[2][4];
        #pragma unroll
        for (int m = 0; m < 2; m++) {
            const __half* Ar = Ash + (warp_m * 32 + m * 16 + g) * LDH + ks * 16 + 2 * t;
            a[m][0] = *(const uint32_t*)Ar;
            a[m][1] = *(const uint32_t*)(Ar + 8 * LDH);
            a[m][2] = *(const uint32_t*)(Ar + 8);
            a[m][3] = *(const uint32_t*)(Ar + 8 * LDH + 8);
        }
        const uint4* Bp = (const uint4*)Bsh + (ks * 8 + warp_n * 4) * 32 + lane;
        #pragma unroll
        for (int jp = 0; jp < 4; jp++) {
            uint4 bb = Bp[jp * 32];
            uint2 blo = make_uint2(bb.x, bb.y);
            uint2 bhi = make_uint2(bb.z, bb.w);
            mma_sync_f16(D[0][jp * 2 + 0], a[0], blo);
            mma_sync_f16(D[1][jp * 2 + 0], a[1], blo);
            mma_sync_f16(D[0][jp * 2 + 1], a[0], bhi);
            mma_sync_f16(D[1][jp * 2 + 1], a[1], bhi);
        }
    }
}

__global__ void __launch_bounds__(256, 2)
pre_merged(const float* __restrict__ embU,
           const float* __restrict__ WaU, const float* __restrict__ WbU,
           const float* __restrict__ biasAU,
           __half* __restrict__ outAU, __half* __restrict__ outBU, int nU,
           const float* __restrict__ embI,
           const float* __restrict__ WaI, const float* __restrict__ WbI,
           const float* __restrict__ biasAI,
           __half* __restrict__ outAI, __half* __restrict__ outBI, int nI,
           int ublocks)
{
    extern __shared__ char smraw[];
    __half* BshA = (__half*)smraw;
    __half* BshB = BshA + BSH_H;
    __half* Ash  = BshB + BSH_H;

    const int tid  = threadIdx.x;
    const int lane = tid & 31, wid = tid >> 5;
    const int warp_m = wid & 3, warp_n = wid >> 2;
    const int g = lane >> 2, t = lane & 3;
    const int cbase = warp_n * 64 + 2 * t;

    const bool second = blockIdx.x >= ublocks;
    const float* emb = second ? embI : embU;
    const float* Wa  = second ? WaI  : WaU;
    const float* Wb  = second ? WbI  : WbU;
    const float* biasA = second ? biasAI : biasAU;
    __half* outA = second ? outAI : outAU;
    __half* outB = second ? outBI : outBU;
    const int rows = second ? nI : nU;
    const int bstart = blockIdx.x - (second ? ublocks : 0);
    const int bcount = second ? (gridDim.x - ublocks) : ublocks;

    pack_B_frag2(BshA, Wa, tid);
    pack_B_frag2(BshB, Wb, tid);

    float2 bA[8];
    #pragma unroll
    for (int j = 0; j < 8; j++)
        bA[j] = ((const float2*)biasA)[(cbase + j * 8) >> 1];
    __syncthreads();

    const int ntiles = (rows + 127) >> 7;
    for (int tile = bstart; tile < ntiles; tile += bcount) {
        const int m0 = tile << 7;
        #pragma unroll
        for (int i = tid; i < 128 * 32; i += 256) {
            int r = i >> 5, c = i & 31;
            int row = m0 + r;
            float4 v = make_float4(0.f, 0.f, 0.f, 0.f);
            if (row < rows) v = __ldcs((const float4*)(emb + (size_t)row * HID) + c);
            __half2 hh[2];
            hh[0] = __floats2half2_rn(v.x, v.y);
            hh[1] = __floats2half2_rn(v.z, v.w);
            *(uint2*)(Ash + r * LDH + c * 4) = *(uint2*)hh;
        }
        __syncthreads();

        #pragma unroll
        for (int pass = 0; pass < 2; pass++) {
            const __half* Bsh = pass ? BshB : BshA;
            __half* outP = pass ? outB : outA;
            float4 D[2][8];
            mma_tile_pair(Ash, Bsh, warp_m, warp_n, lane, D);
            #pragma unroll
            for (int m = 0; m < 2; m++) {
                int r0 = m0 + warp_m * 32 + m * 16 + g;
                #pragma unroll
                for (int j = 0; j < 8; j++) {
                    int c = cbase + j * 8;
                    float2 bb = pass ? make_float2(0.f, 0.f) : bA[j];
                    if (r0 < rows)
                        *(__half2*)(outP + (size_t)r0 * HID + c) =
                            __floats2half2_rn(D[m][j].x + bb.x, D[m][j].y + bb.y);
                    if (r0 + 8 < rows)
                        *(__half2*)(outP + (size_t)(r0 + 8) * HID + c) =
                            __floats2half2_rn(D[m][j].z + bb.x, D[m][j].w + bb.y);
                }
            }
        }
        __syncthreads();
    }
}

// ===========================================================================
// Edge kernel (R13, best known): 64-edge tiles, .cg gather + half2 fused ELU
// (b0 pre-folded), index prefetch, fp32 epilogue, 3 CTAs/SM, 2 barriers/tile.
// SMEM: B packed 32KB | A 64x272B | red[2][256]f | b1/w2(float)
// ===========================================================================
#define TILE    64
#define AROW    272                       // 136 halves
#define EB_B    0
#define EB_A    32768
#define EB_RED  (EB_A + TILE * AROW)      // 50176 (2 x 256 floats)
#define EB_B1S  (EB_RED + 2048)           // 52224
#define EB_W2S  (EB_B1S + 512)            // 52736
#define SMEM_EDGE_BYTES (EB_W2S + 512)    // 53248

struct DecParams {
    const void* src;
    const void* dst;
    const __half* Psrc;
    const __half* Pdst;
    const float *b0, *W1, *b1, *W2, *b2;
    float* out;
};

__global__ void __launch_bounds__(256, 3)
edge_pf(DecParams p0, DecParams p1, int nE)
{
    extern __shared__ char smraw[];
    const uint32_t sbase = smem_u32(smraw);
    float*  redb = (float*)(smraw + EB_RED);
    float*  b1sh = (float*)(smraw + EB_B1S);
    float*  w2sh = (float*)(smraw + EB_W2S);

    const int tid  = threadIdx.x;
    const int lane = tid & 31, wid = tid >> 5;
    const int warp_m = wid & 1;           // 2 x 32 rows
    const int warp_n = wid >> 1;          // 4 x 32 cols
    const int g = lane >> 2, t = lane & 3;

    const int half_grid = gridDim.x >> 1;
    const bool second = blockIdx.x >= half_grid;
    const DecParams p = second ? p1 : p0;
    const int bstart = blockIdx.x - (second ? half_grid : 0);

    // int64 vs int32 indices (values < 2^17 -> int64 high words are 0)
    const int* sw = (const int*)p.src;
    int zz = 0;
    #pragma unroll
    for (int i = 1; i < 64; i += 2) zz |= sw[i];
    const bool is64 = (zz == 0);
    const int* srcw = (const int*)p.src;
    const int* dstw = (const int*)p.dst;
    const int imul = is64 ? 2 : 1;        // index word stride

    pack_B_frag2((__half*)(smraw + EB_B), p.W1, tid);
    if (tid < 128) {
        b1sh[tid] = p.b1[tid];
        w2sh[tid] = p.W2[tid];
    }
    const float bias2 = p.b2[0];
    __syncthreads();

    // gather role: 4 threads per edge; thread covers 32 halves (64B) of the row
    const int grow = tid >> 2;            // edge row 0..63
    const int gq   = tid & 3;             // quarter 0..3
    const uint32_t a_st = sbase + EB_A + (uint32_t)grow * AROW + (uint32_t)gq * 64;

    const int ntiles = (nE + TILE - 1) / TILE;
    const int step = half_grid;

    // prefetch indices for the first tile
    uint32_t si = 0, di = 0;
    if (bstart < ntiles) {
        int e = bstart * TILE + grow;
        if (e < nE) {
            si = (uint32_t)__ldcs(srcw + (size_t)e * imul);
            di = (uint32_t)__ldcs(dstw + (size_t)e * imul);
        }
    }

    int it = 0;
    for (int tile = bstart; tile < ntiles; tile += step, it++) {
        float* red = redb + (it & 1) * 256;

        // --- gather + layer0 (half2 add + elu; b0 already folded) -> A tile
        {
            const char* U = (const char*)p.Psrc + ((size_t)(si << 8)) + gq * 64;
            const char* V = (const char*)p.Pdst + ((size_t)(di << 8)) + gq * 64;

            // prefetch indices for tile n+1 (independent; overlaps everything)
            uint32_t nsi = 0, ndi = 0;
            {
                int nt2 = tile + step;
                if (nt2 < ntiles) {
                    int e2 = nt2 * TILE + grow;
                    if (e2 < nE) {
                        nsi = (uint32_t)__ldcs(srcw + (size_t)e2 * imul);
                        ndi = (uint32_t)__ldcs(dstw + (size_t)e2 * imul);
                    }
                }
            }

            #pragma unroll
            for (int j = 0; j < 4; j++) {
                uint4 u4 = ldcg_u4(U + j * 16);
                uint4 v4 = ldcg_u4(V + j * 16);
                const __half2* uh = (const __half2*)&u4;
                const __half2* vh = (const __half2*)&v4;
                __half2 hh[4];
                #pragma unroll
                for (int q = 0; q < 4; q++)
                    hh[q] = elu_h2(__hadd2(uh[q], vh[q]));
                asm volatile("st.shared.v4.u32 [%0], {%1,%2,%3,%4};"
                             :: "r"(a_st + j * 16),
                                "r"(((uint32_t*)hh)[0]), "r"(((uint32_t*)hh)[1]),
                                "r"(((uint32_t*)hh)[2]), "r"(((uint32_t*)hh)[3])
                             : "memory");
            }
            si = nsi; di = ndi;
        }
        __syncthreads();                  // A ready

        // --- layer-1 GEMM: ldmatrix A, paired-B LDS.128
        float4 D[2][4];
        #pragma unroll
        for (int m = 0; m < 2; m++)
            #pragma unroll
            for (int j = 0; j < 4; j++) D[m][j] = make_float4(0.f, 0.f, 0.f, 0.f);

        const int lrow = lane & 15;
        const int khalf = (lane >> 4) << 3;
        #pragma unroll
        for (int ks = 0; ks < 8; ks++) {
            uint32_t a[2][4];
            #pragma unroll
            for (int m = 0; m < 2; m++) {
                uint32_t addr = sbase + EB_A
                              + (uint32_t)(warp_m * 32 + m * 16 + lrow) * AROW
                              + (uint32_t)(ks * 16 + khalf) * 2;
                asm volatile("ldmatrix.sync.aligned.m8n8.x4.shared.b16 {%0,%1,%2,%3}, [%4];"
                             : "=r"(a[m][0]), "=r"(a[m][1]), "=r"(a[m][2]), "=r"(a[m][3])
                             : "r"(addr));
            }
            const uint4* Bp = (const uint4*)(smraw + EB_B)
                            + (ks * 8 + warp_n * 2) * 32 + lane;
            #pragma unroll
            for (int jp = 0; jp < 2; jp++) {
                uint4 bb = Bp[jp * 32];
                uint2 blo = make_uint2(bb.x, bb.y);
                uint2 bhi = make_uint2(bb.z, bb.w);
                mma_sync_f16(D[0][jp * 2 + 0], a[0], blo);
                mma_sync_f16(D[1][jp * 2 + 0], a[1], blo);
                mma_sync_f16(D[0][jp * 2 + 1], a[0], bhi);
                mma_sync_f16(D[1][jp * 2 + 1], a[1], bhi);
            }
        }

        // --- epilogue: elu(C + b1) . w2, quad-reduce, per-warp_n partials
        #pragma unroll
        for (int m = 0; m < 2; m++) {
            float plo = 0.f, phi = 0.f;
            #pragma unroll
            for (int j = 0; j < 4; j++) {
                int c = warp_n * 32 + j * 8 + 2 * t;
                float2 b1v = *(const float2*)(b1sh + c);
                float2 w2v = *(const float2*)(w2sh + c);
                plo += elu_f(D[m][j].x + b1v.x) * w2v.x
                     + elu_f(D[m][j].y + b1v.y) * w2v.y;
                phi += elu_f(D[m][j].z + b1v.x) * w2v.x
                     + elu_f(D[m][j].w + b1v.y) * w2v.y;
            }
            plo += __shfl_xor_sync(0xffffffffu, plo, 1);
            plo += __shfl_xor_sync(0xffffffffu, plo, 2);
            phi += __shfl_xor_sync(0xffffffffu, phi, 1);
            phi += __shfl_xor_sync(0xffffffffu, phi, 2);
            if (t == 0) {
                int r = warp_m * 32 + m * 16 + g;
                red[warp_n * 64 + r]     = plo;
                red[warp_n * 64 + r + 8] = phi;
            }
        }
        __syncthreads();                  // red ready (also protects A reuse)

        if (tid < TILE) {
            int eo = tile * TILE + tid;
            if (eo < nE) {
                float x = red[tid] + red[64 + tid] + red[128 + tid] + red[192 + tid]
                        + bias2;
                __stcs(p.out + eo, 1.f / (1.f + __expf(-x)));
            }
        }
        // no trailing sync: red is double-buffered; A overwrite is fenced by
        // this iteration's post-epilogue __syncthreads.
    }
}

// ===========================================================================
extern "C" void kernel_launch(void* const* d_in, const int* in_sizes, int n_in,
                              void* d_out, int out_size)
{
    const float* user_emb = (const float*)d_in[0];
    const float* item_emb = (const float*)d_in[1];
    const void*  ui_src   = d_in[2];
    const void*  ui_dst   = d_in[3];
    const void*  iu_src   = d_in[4];
    const void*  iu_dst   = d_in[5];
    const float* W0_ui = (const float*)d_in[6];
    const float* b0_ui = (const float*)d_in[7];
    const float* W1_ui = (const float*)d_in[8];
    const float* b1_ui = (const float*)d_in[9];
    const float* W2_ui = (const float*)d_in[10];
    const float* b2_ui = (const float*)d_in[11];
    const float* W0_iu = (const float*)d_in[12];
    const float* b0_iu = (const float*)d_in[13];
    const float* W1_iu = (const float*)d_in[14];
    const float* b1_iu = (const float*)d_in[15];
    const float* W2_iu = (const float*)d_in[16];
    const float* b2_iu = (const float*)d_in[17];
    float* out = (float*)d_out;

    const int nU = in_sizes[0] / HID;
    const int nI = in_sizes[1] / HID;
    const int nE = in_sizes[2];

    cudaFuncSetAttribute(pre_merged,
                         cudaFuncAttributeMaxDynamicSharedMemorySize, SMEM_PRE_BYTES);
    cudaFuncSetAttribute(edge_pf,
                         cudaFuncAttributeMaxDynamicSharedMemorySize, SMEM_EDGE_BYTES);

    __half *up, *ip;
    cudaGetSymbolAddress((void**)&up, g_user_pre);
    cudaGetSymbolAddress((void**)&ip, g_item_pre);
    __half* U_ui = up;                          // user @ W0_ui[0:128] + b0_ui
    __half* U_iu = up + (size_t)NU_MAX * HID;   // user @ W0_iu[128:256]
    __half* I_ui = ip;                          // item @ W0_ui[128:256]
    __half* I_iu = ip + (size_t)NI_MAX * HID;   // item @ W0_iu[0:128] + b0_iu

    // Grid split proportional to tile counts (user:item ~= nU:nI).
    const int GRID = 296;
    const int ut = (nU + 127) / 128, itt = (nI + 127) / 128;
    int ublocks = (int)((long long)GRID * ut / (ut + itt));
    if (ublocks < 1) ublocks = 1;
    if (ublocks > GRID - 1) ublocks = GRID - 1;

    pre_merged<<<GRID, 256, SMEM_PRE_BYTES>>>(
        user_emb, W0_ui,           W0_iu + 128*128, b0_ui, U_ui, U_iu, nU,
        item_emb, W0_iu,           W0_ui + 128*128, b0_iu, I_iu, I_ui, nI,
        ublocks);

    DecParams p0, p1;
    p0.src = ui_src; p0.dst = ui_dst; p0.Psrc = U_ui; p0.Pdst = I_ui;
    p0.b0 = b0_ui; p0.W1 = W1_ui; p0.b1 = b1_ui; p0.W2 = W2_ui; p0.b2 = b2_ui;
    p0.out = out;
    p1.src = iu_src; p1.dst = iu_dst; p1.Psrc = I_iu; p1.Pdst = U_iu;
    p1.b0 = b0_iu; p1.W1 = W1_iu; p1.b1 = b1_iu; p1.W2 = W2_iu; p1.b2 = b2_iu;
    p1.out = out + nE;

    edge_pf<<<444, 256, SMEM_EDGE_BYTES>>>(p0, p1, nE);
}